// round 1
// baseline (speedup 1.0000x reference)
#include <cuda_runtime.h>
#include <math.h>

#define BQ 32
#define NN 2048

// Scratch (device globals; no allocations allowed)
__device__ float g_h1[BQ * NN * 160];
__device__ float g_h2[BQ * NN * 80];
__device__ float g_h3[BQ * NN * 40];
__device__ float g_h4[BQ * NN * 5];

// ---------------------------------------------------------------------------
// Generic tiled GEMM: C[M,N] = relu(A[M,K] @ W[K,N] + b[N])
// Block tile 64x64, K-tile 16, 256 threads, 4x4 micro-tile (strided).
// ---------------------------------------------------------------------------
__global__ void gemm_bias_relu_kernel(const float* __restrict__ A,
                                      const float* __restrict__ W,
                                      const float* __restrict__ b,
                                      float* __restrict__ C,
                                      int M, int K, int N) {
    const int BM = 64, BN = 64, BK = 16;
    __shared__ float As[BK][BM + 1];
    __shared__ float Ws[BK][BN + 1];
    int tid = threadIdx.x;
    int tx = tid % 16, ty = tid / 16;
    int m0 = blockIdx.y * BM, n0 = blockIdx.x * BN;
    float acc[4][4] = {};
    for (int k0 = 0; k0 < K; k0 += BK) {
        #pragma unroll
        for (int i = 0; i < 4; i++) {
            int idx = tid + i * 256;
            int m = idx / BK, k = idx % BK;
            As[k][m] = A[(long)(m0 + m) * K + k0 + k];
        }
        #pragma unroll
        for (int i = 0; i < 4; i++) {
            int idx = tid + i * 256;
            int k = idx / BN, n = idx % BN;
            Ws[k][n] = (n0 + n < N) ? W[(long)(k0 + k) * N + n0 + n] : 0.0f;
        }
        __syncthreads();
        #pragma unroll
        for (int k = 0; k < BK; k++) {
            float a[4], w[4];
            #pragma unroll
            for (int i = 0; i < 4; i++) a[i] = As[k][ty + 16 * i];
            #pragma unroll
            for (int j = 0; j < 4; j++) w[j] = Ws[k][tx + 16 * j];
            #pragma unroll
            for (int i = 0; i < 4; i++)
                #pragma unroll
                for (int j = 0; j < 4; j++) acc[i][j] += a[i] * w[j];
        }
        __syncthreads();
    }
    #pragma unroll
    for (int i = 0; i < 4; i++)
        #pragma unroll
        for (int j = 0; j < 4; j++) {
            int m = m0 + ty + 16 * i, n = n0 + tx + 16 * j;
            if (n < N) {
                float v = acc[i][j] + b[n];
                C[(long)m * N + n] = v > 0.0f ? v : 0.0f;
            }
        }
}

// ---------------------------------------------------------------------------
// Fused graph conv (flash-attention style).
// Out = relu( softmax_rows(2*H@H^T - |k|^2) @ H @ Wg + bg )
// (the -|q|^2 per-row constant cancels inside softmax)
// Grid: (NN/64, B). 256 threads. Templated on C (in channels), COUT.
// ---------------------------------------------------------------------------
template <int C, int COUT>
__global__ void graph_conv_kernel(const float* __restrict__ H,
                                  const float* __restrict__ Wg,
                                  const float* __restrict__ bg,
                                  float* __restrict__ Out) {
    constexpr int BM = 64;      // query tile
    constexpr int BN = 64;      // key tile
    constexpr int CJ = (C + 15) / 16;
    constexpr int OJ = (COUT + 15) / 16;
    constexpr int QS = C + 1;   // padded row stride

    extern __shared__ float sm[];
    float* Qs  = sm;                       // [64][C+1]   (reused as Agg at end)
    float* Ks  = Qs  + BM * QS;            // [64][C+1]
    float* Ps  = Ks  + BN * QS;            // [64][65]
    float* Wgs = Ps  + BM * 65;            // [C][COUT]
    float* ksq = Wgs + C * COUT;           // [64]
    float* red = ksq + BN;                 // [64][17]

    int tid = threadIdx.x;
    int tx = tid % 16, ty = tid / 16;
    int batch = blockIdx.y;
    int q0 = blockIdx.x * BM;
    const float* Hb = H + (long)batch * NN * C;

    for (int idx = tid; idx < BM * C; idx += 256) {
        int r = idx / C, c = idx % C;
        Qs[r * QS + c] = Hb[(long)(q0 + r) * C + c];
    }
    for (int idx = tid; idx < C * COUT; idx += 256) Wgs[idx] = Wg[idx];

    float m[4], l[4], acc[4][CJ];
    #pragma unroll
    for (int i = 0; i < 4; i++) {
        m[i] = -1e30f; l[i] = 0.0f;
        #pragma unroll
        for (int j = 0; j < CJ; j++) acc[i][j] = 0.0f;
    }

    for (int k0 = 0; k0 < NN; k0 += BN) {
        // load K tile
        for (int idx = tid; idx < BN * C; idx += 256) {
            int r = idx / C, c = idx % C;
            Ks[r * QS + c] = Hb[(long)(k0 + r) * C + c];
        }
        __syncthreads();
        if (tid < BN) {
            float s = 0.0f;
            #pragma unroll
            for (int c = 0; c < C; c++) { float v = Ks[tid * QS + c]; s += v * v; }
            ksq[tid] = s;
        }
        __syncthreads();

        // S = 2*Q@K^T - ksq   (4x4 per thread, strided)
        float s[4][4];
        #pragma unroll
        for (int i = 0; i < 4; i++)
            #pragma unroll
            for (int j = 0; j < 4; j++) s[i][j] = 0.0f;
        #pragma unroll 4
        for (int c = 0; c < C; c++) {
            float qv[4], kv[4];
            #pragma unroll
            for (int i = 0; i < 4; i++) qv[i] = Qs[(ty + 16 * i) * QS + c];
            #pragma unroll
            for (int j = 0; j < 4; j++) kv[j] = Ks[(tx + 16 * j) * QS + c];
            #pragma unroll
            for (int i = 0; i < 4; i++)
                #pragma unroll
                for (int j = 0; j < 4; j++) s[i][j] += qv[i] * kv[j];
        }
        float ksqv[4];
        #pragma unroll
        for (int j = 0; j < 4; j++) ksqv[j] = ksq[tx + 16 * j];
        #pragma unroll
        for (int i = 0; i < 4; i++)
            #pragma unroll
            for (int j = 0; j < 4; j++) s[i][j] = 2.0f * s[i][j] - ksqv[j];

        // row-max reduction across the 16 threads of each row
        #pragma unroll
        for (int i = 0; i < 4; i++) {
            float lm = s[i][0];
            #pragma unroll
            for (int j = 1; j < 4; j++) lm = fmaxf(lm, s[i][j]);
            red[(ty + 16 * i) * 17 + tx] = lm;
        }
        __syncthreads();
        float alpha[4];
        #pragma unroll
        for (int i = 0; i < 4; i++) {
            int r = ty + 16 * i;
            float rm = red[r * 17];
            #pragma unroll
            for (int t = 1; t < 16; t++) rm = fmaxf(rm, red[r * 17 + t]);
            float nm = fmaxf(m[i], rm);
            alpha[i] = __expf(m[i] - nm);
            m[i] = nm;
        }
        __syncthreads();  // all reads of red done before reuse

        // P = exp(S - m), write to smem, partial row sums
        #pragma unroll
        for (int i = 0; i < 4; i++) {
            int r = ty + 16 * i;
            float ls = 0.0f;
            #pragma unroll
            for (int j = 0; j < 4; j++) {
                float p = __expf(s[i][j] - m[i]);
                Ps[r * 65 + tx + 16 * j] = p;
                ls += p;
            }
            red[r * 17 + tx] = ls;
        }
        __syncthreads();
        #pragma unroll
        for (int i = 0; i < 4; i++) {
            int r = ty + 16 * i;
            float rs = 0.0f;
            #pragma unroll
            for (int t = 0; t < 16; t++) rs += red[r * 17 + t];
            l[i] = l[i] * alpha[i] + rs;
            #pragma unroll
            for (int j = 0; j < CJ; j++) acc[i][j] *= alpha[i];
        }

        // O += P @ K  (V == K tile, already resident)
        #pragma unroll 4
        for (int k = 0; k < BN; k++) {
            float pv[4], kv[CJ];
            #pragma unroll
            for (int i = 0; i < 4; i++) pv[i] = Ps[(ty + 16 * i) * 65 + k];
            #pragma unroll
            for (int j = 0; j < CJ; j++) {
                int c = tx + 16 * j;
                kv[j] = (c < C) ? Ks[k * QS + c] : 0.0f;
            }
            #pragma unroll
            for (int i = 0; i < 4; i++)
                #pragma unroll
                for (int j = 0; j < CJ; j++) acc[i][j] += pv[i] * kv[j];
        }
        __syncthreads();
    }

    // normalize; stash Agg into Qs (Q no longer needed)
    #pragma unroll
    for (int i = 0; i < 4; i++) {
        float inv = 1.0f / l[i];
        #pragma unroll
        for (int j = 0; j < CJ; j++) {
            int c = tx + 16 * j;
            if (c < C) Qs[(ty + 16 * i) * QS + c] = acc[i][j] * inv;
        }
    }
    __syncthreads();

    // Out = relu(Agg @ Wg + bg)
    float* Outb = Out + (long)batch * NN * COUT;
    #pragma unroll
    for (int i = 0; i < 4; i++) {
        int r = ty + 16 * i;
        #pragma unroll
        for (int jj = 0; jj < OJ; jj++) {
            int c = tx + 16 * jj;
            if (c < COUT) {
                float v = bg[c];
                #pragma unroll 4
                for (int cc = 0; cc < C; cc++) v += Qs[r * QS + cc] * Wgs[cc * COUT + c];
                Outb[(long)(q0 + r) * COUT + c] = fmaxf(v, 0.0f);
            }
        }
    }
}

// ---------------------------------------------------------------------------
// Mean over nodes -> classifier -> softmax. One block per batch.
// ---------------------------------------------------------------------------
__global__ void finalize_kernel(const float* __restrict__ H4,
                                const float* __restrict__ Wf,
                                const float* __restrict__ bf,
                                float* __restrict__ out) {
    int b = blockIdx.x;
    int tid = threadIdx.x;
    __shared__ float sred[5][256];
    float local[5] = {};
    const float* Hb = H4 + (long)b * NN * 5;
    for (int r = tid; r < NN; r += 256) {
        #pragma unroll
        for (int c = 0; c < 5; c++) local[c] += Hb[r * 5 + c];
    }
    #pragma unroll
    for (int c = 0; c < 5; c++) sred[c][tid] = local[c];
    __syncthreads();
    for (int s = 128; s > 0; s >>= 1) {
        if (tid < s) {
            #pragma unroll
            for (int c = 0; c < 5; c++) sred[c][tid] += sred[c][tid + s];
        }
        __syncthreads();
    }
    if (tid == 0) {
        float mean[5];
        #pragma unroll
        for (int c = 0; c < 5; c++) mean[c] = sred[c][0] / (float)NN;
        float lg[2];
        #pragma unroll
        for (int o = 0; o < 2; o++) {
            float v = bf[o];
            #pragma unroll
            for (int c = 0; c < 5; c++) v += mean[c] * Wf[c * 2 + o];
            lg[o] = v;
        }
        float mx = fmaxf(lg[0], lg[1]);
        float e0 = expf(lg[0] - mx), e1 = expf(lg[1] - mx);
        float inv = 1.0f / (e0 + e1);
        out[b * 2 + 0] = e0 * inv;
        out[b * 2 + 1] = e1 * inv;
    }
}

// ---------------------------------------------------------------------------

static size_t gc_smem_bytes(int C, int COUT) {
    size_t fl = (size_t)64 * (C + 1) * 2   // Qs + Ks
              + (size_t)64 * 65            // Ps
              + (size_t)C * COUT           // Wgs
              + 64                         // ksq
              + (size_t)64 * 17;           // red
    return fl * sizeof(float);
}

extern "C" void kernel_launch(void* const* d_in, const int* in_sizes, int n_in,
                              void* d_out, int out_size) {
    const float* x   = (const float*)d_in[0];
    const float* W1  = (const float*)d_in[1];
    const float* b1  = (const float*)d_in[2];
    const float* W2  = (const float*)d_in[3];
    const float* b2  = (const float*)d_in[4];
    const float* Wg1 = (const float*)d_in[5];
    const float* bg1 = (const float*)d_in[6];
    const float* Wg2 = (const float*)d_in[7];
    const float* bg2 = (const float*)d_in[8];
    const float* Wf  = (const float*)d_in[9];
    const float* bf  = (const float*)d_in[10];
    float* out = (float*)d_out;

    float *h1, *h2, *h3, *h4;
    cudaGetSymbolAddress((void**)&h1, g_h1);
    cudaGetSymbolAddress((void**)&h2, g_h2);
    cudaGetSymbolAddress((void**)&h3, g_h3);
    cudaGetSymbolAddress((void**)&h4, g_h4);

    size_t smem1 = gc_smem_bytes(80, 40);
    size_t smem2 = gc_smem_bytes(40, 5);
    cudaFuncSetAttribute(graph_conv_kernel<80, 40>,
                         cudaFuncAttributeMaxDynamicSharedMemorySize, (int)smem1);
    cudaFuncSetAttribute(graph_conv_kernel<40, 5>,
                         cudaFuncAttributeMaxDynamicSharedMemorySize, (int)smem2);

    const int M = BQ * NN;  // 65536
    dim3 blk(256);

    gemm_bias_relu_kernel<<<dim3((160 + 63) / 64, M / 64), blk>>>(x, W1, b1, h1, M, 320, 160);
    gemm_bias_relu_kernel<<<dim3((80 + 63) / 64, M / 64), blk>>>(h1, W2, b2, h2, M, 160, 80);
    graph_conv_kernel<80, 40><<<dim3(NN / 64, BQ), blk, smem1>>>(h2, Wg1, bg1, h3);
    graph_conv_kernel<40, 5><<<dim3(NN / 64, BQ), blk, smem2>>>(h3, Wg2, bg2, h4);
    finalize_kernel<<<BQ, blk>>>(h4, Wf, bf, out);
}

// round 2
// speedup vs baseline: 1.5863x; 1.5863x over previous
#include <cuda_runtime.h>
#include <math.h>
#include <stdint.h>

#define BQ 32
#define NN 2048

// Scratch (device globals; no allocations allowed)
__device__ float g_h1[BQ * NN * 160];
__device__ float g_h2[BQ * NN * 80];
__device__ float g_h3[BQ * NN * 40];
__device__ float g_h4[BQ * NN * 5];

// ---------------------------------------------------------------------------
// tf32 mma helpers
// ---------------------------------------------------------------------------
__device__ __forceinline__ uint32_t f2tf32(float x) {
    uint32_t r;
    asm("cvt.rna.tf32.f32 %0, %1;" : "=r"(r) : "f"(x));
    return r;
}

__device__ __forceinline__ void mma_tf32(float c[4], const uint32_t a[4],
                                         const uint32_t b[2]) {
    asm volatile(
        "mma.sync.aligned.m16n8k8.row.col.f32.tf32.tf32.f32 "
        "{%0,%1,%2,%3}, {%4,%5,%6,%7}, {%8,%9}, {%0,%1,%2,%3};\n"
        : "+f"(c[0]), "+f"(c[1]), "+f"(c[2]), "+f"(c[3])
        : "r"(a[0]), "r"(a[1]), "r"(a[2]), "r"(a[3]), "r"(b[0]), "r"(b[1]));
}

// ---------------------------------------------------------------------------
// Generic tiled GEMM: C[M,N] = relu(A[M,K] @ W[K,N] + b[N])  (fp32 SIMT)
// ---------------------------------------------------------------------------
__global__ void gemm_bias_relu_kernel(const float* __restrict__ A,
                                      const float* __restrict__ W,
                                      const float* __restrict__ b,
                                      float* __restrict__ C,
                                      int M, int K, int N) {
    const int BM = 64, BN = 64, BK = 16;
    __shared__ float As[BK][BM + 1];
    __shared__ float Ws[BK][BN + 1];
    int tid = threadIdx.x;
    int tx = tid % 16, ty = tid / 16;
    int m0 = blockIdx.y * BM, n0 = blockIdx.x * BN;
    float acc[4][4] = {};
    for (int k0 = 0; k0 < K; k0 += BK) {
        #pragma unroll
        for (int i = 0; i < 4; i++) {
            int idx = tid + i * 256;
            int m = idx / BK, k = idx % BK;
            As[k][m] = A[(long)(m0 + m) * K + k0 + k];
        }
        #pragma unroll
        for (int i = 0; i < 4; i++) {
            int idx = tid + i * 256;
            int k = idx / BN, n = idx % BN;
            Ws[k][n] = (n0 + n < N) ? W[(long)(k0 + k) * N + n0 + n] : 0.0f;
        }
        __syncthreads();
        #pragma unroll
        for (int k = 0; k < BK; k++) {
            float a[4], w[4];
            #pragma unroll
            for (int i = 0; i < 4; i++) a[i] = As[k][ty + 16 * i];
            #pragma unroll
            for (int j = 0; j < 4; j++) w[j] = Ws[k][tx + 16 * j];
            #pragma unroll
            for (int i = 0; i < 4; i++)
                #pragma unroll
                for (int j = 0; j < 4; j++) acc[i][j] += a[i] * w[j];
        }
        __syncthreads();
    }
    #pragma unroll
    for (int i = 0; i < 4; i++)
        #pragma unroll
        for (int j = 0; j < 4; j++) {
            int m = m0 + ty + 16 * i, n = n0 + tx + 16 * j;
            if (n < N) {
                float v = acc[i][j] + b[n];
                C[(long)m * N + n] = v > 0.0f ? v : 0.0f;
            }
        }
}

// ---------------------------------------------------------------------------
// Fused graph conv, tensor-core (tf32 mma) flash-attention style.
// logits = 2*Q@H^T - |k|^2  (the -|q|^2 row constant cancels in softmax)
// Out = relu( softmax(logits) @ H @ Wg + bg )
// 128 threads = 4 warps; warp w owns query rows [16w, 16w+16).
// S computed in tf32x2 (3 mma), O = P@K in plain tf32.
// ---------------------------------------------------------------------------
template <int C, int COUT>
__global__ void graph_conv_mma_kernel(const float* __restrict__ H,
                                      const float* __restrict__ Wg,
                                      const float* __restrict__ bg,
                                      float* __restrict__ Out) {
    constexpr int QS = C + 1;        // padded row stride (odd)
    constexpr int NT = C / 8;        // n-tiles of acc / k-steps of S

    extern __shared__ float sm[];
    float* Qs  = sm;                 // [64][QS]  holds 2*Q; reused as Agg
    float* Ks  = Qs + 64 * QS;       // [64][QS]
    float* Ps  = Ks + 64 * QS;       // [64][65]
    float* Wgs = Ps + 64 * 65;       // [C][COUT]
    float* ksq = Wgs + C * COUT;     // [64]

    const int tid = threadIdx.x;
    const int lane = tid & 31, warp = tid >> 5;
    const int g = lane >> 2, t = lane & 3;
    const int batch = blockIdx.y;
    const int q0 = blockIdx.x * 64;
    const float* Hb = H + (long)batch * NN * C;

    for (int idx = tid; idx < 64 * C; idx += 128) {
        int r = idx / C, c = idx % C;
        Qs[r * QS + c] = 2.0f * Hb[(long)(q0 + r) * C + c];
    }
    for (int idx = tid; idx < C * COUT; idx += 128) Wgs[idx] = Wg[idx];

    const int row0 = warp * 16 + g;  // rows row0 and row0+8 belong to this thread

    float acc[NT][4];
    #pragma unroll
    for (int j = 0; j < NT; j++) {
        acc[j][0] = acc[j][1] = acc[j][2] = acc[j][3] = 0.0f;
    }
    float m0r = -1e30f, m1r = -1e30f, l0r = 0.0f, l1r = 0.0f;

    for (int k0 = 0; k0 < NN; k0 += 64) {
        // load K tile
        for (int idx = tid; idx < 64 * C; idx += 128) {
            int r = idx / C, c = idx % C;
            Ks[r * QS + c] = Hb[(long)(k0 + r) * C + c];
        }
        __syncthreads();
        if (tid < 64) {
            float ss = 0.0f;
            #pragma unroll
            for (int c = 0; c < C; c++) { float v = Ks[tid * QS + c]; ss += v * v; }
            ksq[tid] = ss;
        }
        __syncthreads();

        // ---- S = (2Q) @ K^T  via tf32x2 ----
        float s[8][4];
        #pragma unroll
        for (int j = 0; j < 8; j++) s[j][0] = s[j][1] = s[j][2] = s[j][3] = 0.0f;

        #pragma unroll 1
        for (int kk = 0; kk < C; kk += 8) {
            float af[4];
            af[0] = Qs[row0 * QS + kk + t];
            af[1] = Qs[(row0 + 8) * QS + kk + t];
            af[2] = Qs[row0 * QS + kk + t + 4];
            af[3] = Qs[(row0 + 8) * QS + kk + t + 4];
            uint32_t ah[4], al[4];
            #pragma unroll
            for (int i = 0; i < 4; i++) {
                ah[i] = f2tf32(af[i]);
                al[i] = f2tf32(af[i] - __uint_as_float(ah[i]));
            }
            #pragma unroll
            for (int j = 0; j < 8; j++) {
                float bf0 = Ks[(8 * j + g) * QS + kk + t];
                float bf1 = Ks[(8 * j + g) * QS + kk + t + 4];
                uint32_t bh[2], bl[2];
                bh[0] = f2tf32(bf0); bl[0] = f2tf32(bf0 - __uint_as_float(bh[0]));
                bh[1] = f2tf32(bf1); bl[1] = f2tf32(bf1 - __uint_as_float(bh[1]));
                mma_tf32(s[j], ah, bl);
                mma_tf32(s[j], al, bh);
                mma_tf32(s[j], ah, bh);
            }
        }

        // ---- logits, online softmax ----
        float mx0 = -1e30f, mx1 = -1e30f;
        #pragma unroll
        for (int j = 0; j < 8; j++) {
            float kv0 = ksq[8 * j + 2 * t], kv1 = ksq[8 * j + 2 * t + 1];
            s[j][0] -= kv0; s[j][1] -= kv1;
            s[j][2] -= kv0; s[j][3] -= kv1;
            mx0 = fmaxf(mx0, fmaxf(s[j][0], s[j][1]));
            mx1 = fmaxf(mx1, fmaxf(s[j][2], s[j][3]));
        }
        mx0 = fmaxf(mx0, __shfl_xor_sync(0xffffffffu, mx0, 1));
        mx0 = fmaxf(mx0, __shfl_xor_sync(0xffffffffu, mx0, 2));
        mx1 = fmaxf(mx1, __shfl_xor_sync(0xffffffffu, mx1, 1));
        mx1 = fmaxf(mx1, __shfl_xor_sync(0xffffffffu, mx1, 2));
        float nm0 = fmaxf(m0r, mx0), nm1 = fmaxf(m1r, mx1);
        float al0 = __expf(m0r - nm0), al1 = __expf(m1r - nm1);
        m0r = nm0; m1r = nm1;

        float sum0 = 0.0f, sum1 = 0.0f;
        #pragma unroll
        for (int j = 0; j < 8; j++) {
            float p0 = __expf(s[j][0] - nm0), p1 = __expf(s[j][1] - nm0);
            float p2 = __expf(s[j][2] - nm1), p3 = __expf(s[j][3] - nm1);
            sum0 += p0 + p1; sum1 += p2 + p3;
            Ps[row0 * 65 + 8 * j + 2 * t]       = p0;
            Ps[row0 * 65 + 8 * j + 2 * t + 1]   = p1;
            Ps[(row0 + 8) * 65 + 8 * j + 2 * t]     = p2;
            Ps[(row0 + 8) * 65 + 8 * j + 2 * t + 1] = p3;
        }
        sum0 += __shfl_xor_sync(0xffffffffu, sum0, 1);
        sum0 += __shfl_xor_sync(0xffffffffu, sum0, 2);
        sum1 += __shfl_xor_sync(0xffffffffu, sum1, 1);
        sum1 += __shfl_xor_sync(0xffffffffu, sum1, 2);
        l0r = l0r * al0 + sum0;
        l1r = l1r * al1 + sum1;
        #pragma unroll
        for (int j = 0; j < NT; j++) {
            acc[j][0] *= al0; acc[j][1] *= al0;
            acc[j][2] *= al1; acc[j][3] *= al1;
        }
        __syncwarp();

        // ---- O += P @ K (plain tf32) ----
        #pragma unroll 1
        for (int kb = 0; kb < 8; kb++) {
            uint32_t ap[4];
            ap[0] = f2tf32(Ps[row0 * 65 + 8 * kb + t]);
            ap[1] = f2tf32(Ps[(row0 + 8) * 65 + 8 * kb + t]);
            ap[2] = f2tf32(Ps[row0 * 65 + 8 * kb + t + 4]);
            ap[3] = f2tf32(Ps[(row0 + 8) * 65 + 8 * kb + t + 4]);
            #pragma unroll
            for (int j = 0; j < NT; j++) {
                uint32_t bp[2];
                bp[0] = f2tf32(Ks[(8 * kb + t) * QS + 8 * j + g]);
                bp[1] = f2tf32(Ks[(8 * kb + t + 4) * QS + 8 * j + g]);
                mma_tf32(acc[j], ap, bp);
            }
        }
        __syncthreads();
    }

    // normalize; stash Agg into Qs
    {
        float inv0 = 1.0f / l0r, inv1 = 1.0f / l1r;
        #pragma unroll
        for (int j = 0; j < NT; j++) {
            Qs[row0 * QS + 8 * j + 2 * t]       = acc[j][0] * inv0;
            Qs[row0 * QS + 8 * j + 2 * t + 1]   = acc[j][1] * inv0;
            Qs[(row0 + 8) * QS + 8 * j + 2 * t]     = acc[j][2] * inv1;
            Qs[(row0 + 8) * QS + 8 * j + 2 * t + 1] = acc[j][3] * inv1;
        }
    }
    __syncthreads();

    // Out = relu(Agg @ Wg + bg)   (exact fp32)
    float* Outb = Out + (long)batch * NN * COUT + (long)q0 * COUT;
    for (int idx = tid; idx < 64 * COUT; idx += 128) {
        int r = idx / COUT, o = idx % COUT;
        float v = bg[o];
        #pragma unroll 4
        for (int c = 0; c < C; c++) v += Qs[r * QS + c] * Wgs[c * COUT + o];
        Outb[r * COUT + o] = fmaxf(v, 0.0f);
    }
}

// ---------------------------------------------------------------------------
// Mean over nodes -> classifier -> softmax. One block per batch.
// ---------------------------------------------------------------------------
__global__ void finalize_kernel(const float* __restrict__ H4,
                                const float* __restrict__ Wf,
                                const float* __restrict__ bf,
                                float* __restrict__ out) {
    int b = blockIdx.x;
    int tid = threadIdx.x;
    __shared__ float sred[5][256];
    float local[5] = {};
    const float* Hb = H4 + (long)b * NN * 5;
    for (int r = tid; r < NN; r += 256) {
        #pragma unroll
        for (int c = 0; c < 5; c++) local[c] += Hb[r * 5 + c];
    }
    #pragma unroll
    for (int c = 0; c < 5; c++) sred[c][tid] = local[c];
    __syncthreads();
    for (int s = 128; s > 0; s >>= 1) {
        if (tid < s) {
            #pragma unroll
            for (int c = 0; c < 5; c++) sred[c][tid] += sred[c][tid + s];
        }
        __syncthreads();
    }
    if (tid == 0) {
        float mean[5];
        #pragma unroll
        for (int c = 0; c < 5; c++) mean[c] = sred[c][0] / (float)NN;
        float lg[2];
        #pragma unroll
        for (int o = 0; o < 2; o++) {
            float v = bf[o];
            #pragma unroll
            for (int c = 0; c < 5; c++) v += mean[c] * Wf[c * 2 + o];
            lg[o] = v;
        }
        float mx = fmaxf(lg[0], lg[1]);
        float e0 = expf(lg[0] - mx), e1 = expf(lg[1] - mx);
        float inv = 1.0f / (e0 + e1);
        out[b * 2 + 0] = e0 * inv;
        out[b * 2 + 1] = e1 * inv;
    }
}

// ---------------------------------------------------------------------------

static size_t gc_smem_bytes(int C, int COUT) {
    size_t fl = (size_t)64 * (C + 1) * 2   // Qs + Ks
              + (size_t)64 * 65            // Ps
              + (size_t)C * COUT           // Wgs
              + 64;                        // ksq
    return fl * sizeof(float);
}

extern "C" void kernel_launch(void* const* d_in, const int* in_sizes, int n_in,
                              void* d_out, int out_size) {
    const float* x   = (const float*)d_in[0];
    const float* W1  = (const float*)d_in[1];
    const float* b1  = (const float*)d_in[2];
    const float* W2  = (const float*)d_in[3];
    const float* b2  = (const float*)d_in[4];
    const float* Wg1 = (const float*)d_in[5];
    const float* bg1 = (const float*)d_in[6];
    const float* Wg2 = (const float*)d_in[7];
    const float* bg2 = (const float*)d_in[8];
    const float* Wf  = (const float*)d_in[9];
    const float* bf  = (const float*)d_in[10];
    float* out = (float*)d_out;

    float *h1, *h2, *h3, *h4;
    cudaGetSymbolAddress((void**)&h1, g_h1);
    cudaGetSymbolAddress((void**)&h2, g_h2);
    cudaGetSymbolAddress((void**)&h3, g_h3);
    cudaGetSymbolAddress((void**)&h4, g_h4);

    size_t smem1 = gc_smem_bytes(80, 40);
    size_t smem2 = gc_smem_bytes(40, 5);
    cudaFuncSetAttribute(graph_conv_mma_kernel<80, 40>,
                         cudaFuncAttributeMaxDynamicSharedMemorySize, (int)smem1);
    cudaFuncSetAttribute(graph_conv_mma_kernel<40, 5>,
                         cudaFuncAttributeMaxDynamicSharedMemorySize, (int)smem2);

    const int M = BQ * NN;  // 65536
    gemm_bias_relu_kernel<<<dim3((160 + 63) / 64, M / 64), 256>>>(x, W1, b1, h1, M, 320, 160);
    gemm_bias_relu_kernel<<<dim3((80 + 63) / 64, M / 64), 256>>>(h1, W2, b2, h2, M, 160, 80);
    graph_conv_mma_kernel<80, 40><<<dim3(NN / 64, BQ), 128, smem1>>>(h2, Wg1, bg1, h3);
    graph_conv_mma_kernel<40, 5><<<dim3(NN / 64, BQ), 128, smem2>>>(h3, Wg2, bg2, h4);
    finalize_kernel<<<BQ, 256>>>(h4, Wf, bf, out);
}

// round 3
// speedup vs baseline: 1.6418x; 1.0350x over previous
#include <cuda_runtime.h>
#include <math.h>
#include <stdint.h>

#define BQ 32
#define NN 2048

// Scratch (device globals; no allocations allowed)
__device__ float g_h1[BQ * NN * 160];
__device__ float g_h2[BQ * NN * 80];
__device__ float g_h3[BQ * NN * 40];
__device__ float g_h4[BQ * NN * 5];
__device__ uint2 g_pair1[BQ * NN * 80];   // tf32 (hi,lo) of h2
__device__ uint2 g_pair2[BQ * NN * 40];   // tf32 (hi,lo) of h3
__device__ unsigned g_v1[BQ * NN * 40];   // tf32 of h2@Wg1
__device__ unsigned g_v2[BQ * NN * 8];    // tf32 of h3@Wg2 (padded to 8)
__device__ float g_ksq[BQ * NN];

// ---------------------------------------------------------------------------
// tf32 helpers
// ---------------------------------------------------------------------------
__device__ __forceinline__ uint32_t f2tf32(float x) {
    uint32_t r;
    asm("cvt.rna.tf32.f32 %0, %1;" : "=r"(r) : "f"(x));
    return r;
}

__device__ __forceinline__ void mma_tf32(float c[4], const uint32_t a[4],
                                         const uint32_t b[2]) {
    asm volatile(
        "mma.sync.aligned.m16n8k8.row.col.f32.tf32.tf32.f32 "
        "{%0,%1,%2,%3}, {%4,%5,%6,%7}, {%8,%9}, {%0,%1,%2,%3};\n"
        : "+f"(c[0]), "+f"(c[1]), "+f"(c[2]), "+f"(c[3])
        : "r"(a[0]), "r"(a[1]), "r"(a[2]), "r"(a[3]), "r"(b[0]), "r"(b[1]));
}

// ---------------------------------------------------------------------------
// Generic tiled GEMM: C[M,N] = relu(A[M,K] @ W[K,N] + b[N])  (fp32 SIMT)
// ---------------------------------------------------------------------------
__global__ void gemm_bias_relu_kernel(const float* __restrict__ A,
                                      const float* __restrict__ W,
                                      const float* __restrict__ b,
                                      float* __restrict__ C,
                                      int M, int K, int N) {
    const int BM = 64, BN = 64, BK = 16;
    __shared__ float As[BK][BM + 1];
    __shared__ float Ws[BK][BN + 1];
    int tid = threadIdx.x;
    int tx = tid % 16, ty = tid / 16;
    int m0 = blockIdx.y * BM, n0 = blockIdx.x * BN;
    float acc[4][4] = {};
    for (int k0 = 0; k0 < K; k0 += BK) {
        #pragma unroll
        for (int i = 0; i < 4; i++) {
            int idx = tid + i * 256;
            int m = idx / BK, k = idx % BK;
            As[k][m] = A[(long)(m0 + m) * K + k0 + k];
        }
        #pragma unroll
        for (int i = 0; i < 4; i++) {
            int idx = tid + i * 256;
            int k = idx / BN, n = idx % BN;
            Ws[k][n] = (n0 + n < N) ? W[(long)(k0 + k) * N + n0 + n] : 0.0f;
        }
        __syncthreads();
        #pragma unroll
        for (int k = 0; k < BK; k++) {
            float a[4], w[4];
            #pragma unroll
            for (int i = 0; i < 4; i++) a[i] = As[k][ty + 16 * i];
            #pragma unroll
            for (int j = 0; j < 4; j++) w[j] = Ws[k][tx + 16 * j];
            #pragma unroll
            for (int i = 0; i < 4; i++)
                #pragma unroll
                for (int j = 0; j < 4; j++) acc[i][j] += a[i] * w[j];
        }
        __syncthreads();
    }
    #pragma unroll
    for (int i = 0; i < 4; i++)
        #pragma unroll
        for (int j = 0; j < 4; j++) {
            int m = m0 + ty + 16 * i, n = n0 + tx + 16 * j;
            if (n < N) {
                float v = acc[i][j] + b[n];
                C[(long)m * N + n] = v > 0.0f ? v : 0.0f;
            }
        }
}

// ---------------------------------------------------------------------------
// Prep per graph-conv layer: Hpair = tf32 hi/lo split of H, ksq = |h|^2,
// V = tf32(H @ Wg) padded to VN columns.
// Grid: (NN/64, B), 256 threads.
// ---------------------------------------------------------------------------
template <int C, int COUT, int VN>
__global__ void gc_prep_kernel(const float* __restrict__ H,
                               const float* __restrict__ Wg,
                               uint2* __restrict__ Hpair,
                               unsigned* __restrict__ Vhi,
                               float* __restrict__ ksq_g) {
    __shared__ float Hs[64][C + 1];
    __shared__ float Wgs[C * COUT];
    const int tid = threadIdx.x;
    const int batch = blockIdx.y;
    const int n0 = blockIdx.x * 64;
    const float* Hb = H + (size_t)batch * NN * C + (size_t)n0 * C;

    for (int idx = tid; idx < 64 * C; idx += 256) {
        Hs[idx / C][idx % C] = Hb[idx];
    }
    for (int idx = tid; idx < C * COUT; idx += 256) Wgs[idx] = Wg[idx];
    __syncthreads();

    uint2* Pb = Hpair + (size_t)batch * NN * C + (size_t)n0 * C;
    for (int idx = tid; idx < 64 * C; idx += 256) {
        float v = Hs[idx / C][idx % C];
        uint32_t hi = f2tf32(v);
        uint32_t lo = f2tf32(v - __uint_as_float(hi));
        Pb[idx] = make_uint2(hi, lo);
    }
    if (tid < 64) {
        float s = 0.0f;
        #pragma unroll 4
        for (int c = 0; c < C; c++) { float v = Hs[tid][c]; s += v * v; }
        ksq_g[(size_t)batch * NN + n0 + tid] = s;
    }
    unsigned* Vb = Vhi + (size_t)batch * NN * VN + (size_t)n0 * VN;
    for (int idx = tid; idx < 64 * VN; idx += 256) {
        int r = idx / VN, o = idx % VN;
        float v = 0.0f;
        if (o < COUT) {
            #pragma unroll 4
            for (int c = 0; c < C; c++) v += Hs[r][c] * Wgs[c * COUT + o];
        }
        Vb[idx] = f2tf32(v);
    }
}

// ---------------------------------------------------------------------------
// Graph-conv attention kernel (tensor core, projected-space aggregation).
// logits = 2*(q.k) - |k|^2 ;  Out = relu(softmax(logits) @ V + bg)
// 128 threads = 4 warps, 64 query rows per block, 64-key tiles.
// S in tf32x2 (3 mma), O = P@V in plain tf32. P refragmented via shfl.
// ---------------------------------------------------------------------------
template <int C, int COUT, int VN>
__global__ void gc_attn_kernel(const uint2* __restrict__ Hpair,
                               const float* __restrict__ ksq_g,
                               const unsigned* __restrict__ Vhi,
                               const float* __restrict__ bg,
                               float* __restrict__ Out) {
    constexpr int CP = C + 4;     // uint2 stride (CP % 16 == 4: conflict-free LDS.64)
    constexpr int VP = VN;        // VN in {40, 8}: VN % 32 == 8: conflict-free
    constexpr int NT = VN / 8;

    extern __shared__ char smraw[];
    uint2* Qs = (uint2*)smraw;                    // [64][CP]
    uint2* Ks = Qs + 64 * CP;                     // [64][CP]
    unsigned* Vs = (unsigned*)(Ks + 64 * CP);     // [64][VP]
    float* ksqs = (float*)(Vs + 64 * VP);         // [64]

    const int tid = threadIdx.x;
    const int lane = tid & 31, warp = tid >> 5;
    const int g = lane >> 2, t = lane & 3;
    const int batch = blockIdx.y;
    const int q0 = blockIdx.x * 64;
    const uint2* Hb = Hpair + (size_t)batch * NN * C;
    const unsigned* Vb = Vhi + (size_t)batch * NN * VN;
    const float* ksqb = ksq_g + (size_t)batch * NN;

    // stage Q (once)
    for (int idx = tid; idx < 64 * C; idx += 128) {
        int r = idx / C, c = idx % C;
        Qs[r * CP + c] = Hb[(size_t)(q0 + r) * C + c];
    }

    const int row0 = warp * 16 + g;
    const int src0 = (lane & ~3) | (t >> 1);
    const int src2 = src0 + 2;
    const bool odd = (t & 1);

    float acc[NT][4];
    #pragma unroll
    for (int j = 0; j < NT; j++)
        acc[j][0] = acc[j][1] = acc[j][2] = acc[j][3] = 0.0f;
    float m0r = -1e30f, m1r = -1e30f, l0r = 0.0f, l1r = 0.0f;

    for (int k0 = 0; k0 < NN; k0 += 64) {
        // stage K, V, ksq tile
        for (int idx = tid; idx < 64 * C; idx += 128) {
            int r = idx / C, c = idx % C;
            Ks[r * CP + c] = Hb[(size_t)(k0 + r) * C + c];
        }
        for (int idx = tid; idx < 64 * VN; idx += 128) {
            int r = idx / VN, c = idx % VN;
            Vs[r * VP + c] = Vb[(size_t)(k0 + r) * VN + c];
        }
        if (tid < 64) ksqs[tid] = ksqb[k0 + tid];
        __syncthreads();

        // ---- S = Q @ K^T (tf32x2) ----
        float s[8][4];
        #pragma unroll
        for (int j = 0; j < 8; j++) s[j][0] = s[j][1] = s[j][2] = s[j][3] = 0.0f;

        #pragma unroll 1
        for (int kk = 0; kk < C; kk += 8) {
            uint2 qa0 = Qs[row0 * CP + kk + t];
            uint2 qa1 = Qs[(row0 + 8) * CP + kk + t];
            uint2 qa2 = Qs[row0 * CP + kk + t + 4];
            uint2 qa3 = Qs[(row0 + 8) * CP + kk + t + 4];
            uint32_t ah[4] = {qa0.x, qa1.x, qa2.x, qa3.x};
            uint32_t al[4] = {qa0.y, qa1.y, qa2.y, qa3.y};
            #pragma unroll
            for (int j = 0; j < 8; j++) {
                uint2 kb0 = Ks[(8 * j + g) * CP + kk + t];
                uint2 kb1 = Ks[(8 * j + g) * CP + kk + t + 4];
                uint32_t bh[2] = {kb0.x, kb1.x};
                uint32_t bl[2] = {kb0.y, kb1.y};
                mma_tf32(s[j], ah, bl);
                mma_tf32(s[j], al, bh);
                mma_tf32(s[j], ah, bh);
            }
        }

        // ---- logits = 2*s - ksq, online softmax ----
        float mx0 = -1e30f, mx1 = -1e30f;
        #pragma unroll
        for (int j = 0; j < 8; j++) {
            float kv0 = ksqs[8 * j + 2 * t], kv1 = ksqs[8 * j + 2 * t + 1];
            s[j][0] = 2.0f * s[j][0] - kv0;
            s[j][1] = 2.0f * s[j][1] - kv1;
            s[j][2] = 2.0f * s[j][2] - kv0;
            s[j][3] = 2.0f * s[j][3] - kv1;
            mx0 = fmaxf(mx0, fmaxf(s[j][0], s[j][1]));
            mx1 = fmaxf(mx1, fmaxf(s[j][2], s[j][3]));
        }
        mx0 = fmaxf(mx0, __shfl_xor_sync(0xffffffffu, mx0, 1));
        mx0 = fmaxf(mx0, __shfl_xor_sync(0xffffffffu, mx0, 2));
        mx1 = fmaxf(mx1, __shfl_xor_sync(0xffffffffu, mx1, 1));
        mx1 = fmaxf(mx1, __shfl_xor_sync(0xffffffffu, mx1, 2));
        float nm0 = fmaxf(m0r, mx0), nm1 = fmaxf(m1r, mx1);
        float al0 = __expf(m0r - nm0), al1 = __expf(m1r - nm1);
        m0r = nm0; m1r = nm1;

        float sum0 = 0.0f, sum1 = 0.0f;
        #pragma unroll
        for (int j = 0; j < 8; j++) {
            s[j][0] = __expf(s[j][0] - nm0);
            s[j][1] = __expf(s[j][1] - nm0);
            s[j][2] = __expf(s[j][2] - nm1);
            s[j][3] = __expf(s[j][3] - nm1);
            sum0 += s[j][0] + s[j][1];
            sum1 += s[j][2] + s[j][3];
        }
        sum0 += __shfl_xor_sync(0xffffffffu, sum0, 1);
        sum0 += __shfl_xor_sync(0xffffffffu, sum0, 2);
        sum1 += __shfl_xor_sync(0xffffffffu, sum1, 1);
        sum1 += __shfl_xor_sync(0xffffffffu, sum1, 2);
        l0r = l0r * al0 + sum0;
        l1r = l1r * al1 + sum1;
        #pragma unroll
        for (int j = 0; j < NT; j++) {
            acc[j][0] *= al0; acc[j][1] *= al0;
            acc[j][2] *= al1; acc[j][3] *= al1;
        }

        // ---- O += P @ V (plain tf32); P refragmented C-frag -> A-frag via shfl ----
        #pragma unroll
        for (int kb = 0; kb < 8; kb++) {
            uint32_t u0 = f2tf32(s[kb][0]);
            uint32_t u1 = f2tf32(s[kb][1]);
            uint32_t u2 = f2tf32(s[kb][2]);
            uint32_t u3 = f2tf32(s[kb][3]);
            uint32_t e0  = __shfl_sync(0xffffffffu, u0, src0);
            uint32_t o0  = __shfl_sync(0xffffffffu, u1, src0);
            uint32_t e0b = __shfl_sync(0xffffffffu, u0, src2);
            uint32_t o0b = __shfl_sync(0xffffffffu, u1, src2);
            uint32_t e1  = __shfl_sync(0xffffffffu, u2, src0);
            uint32_t o1  = __shfl_sync(0xffffffffu, u3, src0);
            uint32_t e1b = __shfl_sync(0xffffffffu, u2, src2);
            uint32_t o1b = __shfl_sync(0xffffffffu, u3, src2);
            uint32_t ap[4];
            ap[0] = odd ? o0 : e0;    // P[g][8kb+t]
            ap[1] = odd ? o1 : e1;    // P[g+8][8kb+t]
            ap[2] = odd ? o0b : e0b;  // P[g][8kb+t+4]
            ap[3] = odd ? o1b : e1b;  // P[g+8][8kb+t+4]
            #pragma unroll
            for (int j = 0; j < NT; j++) {
                uint32_t bp[2];
                bp[0] = Vs[(8 * kb + t) * VP + 8 * j + g];
                bp[1] = Vs[(8 * kb + t + 4) * VP + 8 * j + g];
                mma_tf32(acc[j], ap, bp);
            }
        }
        __syncthreads();  // Ks/Vs reuse next iteration
    }

    // ---- epilogue: Out = relu(acc/l + bg) ----
    float inv0 = 1.0f / l0r, inv1 = 1.0f / l1r;
    float* Outb = Out + (size_t)batch * NN * COUT + (size_t)q0 * COUT;
    #pragma unroll
    for (int j = 0; j < NT; j++) {
        int c0 = 8 * j + 2 * t, c1 = c0 + 1;
        if (c0 < COUT) {
            float b0v = __ldg(&bg[c0]);
            Outb[row0 * COUT + c0] = fmaxf(acc[j][0] * inv0 + b0v, 0.0f);
            Outb[(row0 + 8) * COUT + c0] = fmaxf(acc[j][2] * inv1 + b0v, 0.0f);
        }
        if (c1 < COUT) {
            float b1v = __ldg(&bg[c1]);
            Outb[row0 * COUT + c1] = fmaxf(acc[j][1] * inv0 + b1v, 0.0f);
            Outb[(row0 + 8) * COUT + c1] = fmaxf(acc[j][3] * inv1 + b1v, 0.0f);
        }
    }
}

// ---------------------------------------------------------------------------
// Mean over nodes -> classifier -> softmax. One block per batch.
// ---------------------------------------------------------------------------
__global__ void finalize_kernel(const float* __restrict__ H4,
                                const float* __restrict__ Wf,
                                const float* __restrict__ bf,
                                float* __restrict__ out) {
    int b = blockIdx.x;
    int tid = threadIdx.x;
    __shared__ float sred[5][256];
    float local[5] = {};
    const float* Hb = H4 + (long)b * NN * 5;
    for (int r = tid; r < NN; r += 256) {
        #pragma unroll
        for (int c = 0; c < 5; c++) local[c] += Hb[r * 5 + c];
    }
    #pragma unroll
    for (int c = 0; c < 5; c++) sred[c][tid] = local[c];
    __syncthreads();
    for (int s = 128; s > 0; s >>= 1) {
        if (tid < s) {
            #pragma unroll
            for (int c = 0; c < 5; c++) sred[c][tid] += sred[c][tid + s];
        }
        __syncthreads();
    }
    if (tid == 0) {
        float mean[5];
        #pragma unroll
        for (int c = 0; c < 5; c++) mean[c] = sred[c][0] / (float)NN;
        float lg[2];
        #pragma unroll
        for (int o = 0; o < 2; o++) {
            float v = bf[o];
            #pragma unroll
            for (int c = 0; c < 5; c++) v += mean[c] * Wf[c * 2 + o];
            lg[o] = v;
        }
        float mx = fmaxf(lg[0], lg[1]);
        float e0 = expf(lg[0] - mx), e1 = expf(lg[1] - mx);
        float inv = 1.0f / (e0 + e1);
        out[b * 2 + 0] = e0 * inv;
        out[b * 2 + 1] = e1 * inv;
    }
}

// ---------------------------------------------------------------------------

static size_t attn_smem_bytes(int C, int VN) {
    return (size_t)64 * (C + 4) * 8 * 2 + (size_t)64 * VN * 4 + 64 * 4;
}

extern "C" void kernel_launch(void* const* d_in, const int* in_sizes, int n_in,
                              void* d_out, int out_size) {
    const float* x   = (const float*)d_in[0];
    const float* W1  = (const float*)d_in[1];
    const float* b1  = (const float*)d_in[2];
    const float* W2  = (const float*)d_in[3];
    const float* b2  = (const float*)d_in[4];
    const float* Wg1 = (const float*)d_in[5];
    const float* bg1 = (const float*)d_in[6];
    const float* Wg2 = (const float*)d_in[7];
    const float* bg2 = (const float*)d_in[8];
    const float* Wf  = (const float*)d_in[9];
    const float* bf  = (const float*)d_in[10];
    float* out = (float*)d_out;

    float *h1, *h2, *h3, *h4, *ksq;
    uint2 *p1, *p2;
    unsigned *v1, *v2;
    cudaGetSymbolAddress((void**)&h1, g_h1);
    cudaGetSymbolAddress((void**)&h2, g_h2);
    cudaGetSymbolAddress((void**)&h3, g_h3);
    cudaGetSymbolAddress((void**)&h4, g_h4);
    cudaGetSymbolAddress((void**)&p1, g_pair1);
    cudaGetSymbolAddress((void**)&p2, g_pair2);
    cudaGetSymbolAddress((void**)&v1, g_v1);
    cudaGetSymbolAddress((void**)&v2, g_v2);
    cudaGetSymbolAddress((void**)&ksq, g_ksq);

    size_t smem1 = attn_smem_bytes(80, 40);
    size_t smem2 = attn_smem_bytes(40, 8);
    cudaFuncSetAttribute(gc_attn_kernel<80, 40, 40>,
                         cudaFuncAttributeMaxDynamicSharedMemorySize, (int)smem1);
    cudaFuncSetAttribute(gc_attn_kernel<40, 5, 8>,
                         cudaFuncAttributeMaxDynamicSharedMemorySize, (int)smem2);

    const int M = BQ * NN;  // 65536
    dim3 gtile(NN / 64, BQ);

    gemm_bias_relu_kernel<<<dim3((160 + 63) / 64, M / 64), 256>>>(x, W1, b1, h1, M, 320, 160);
    gemm_bias_relu_kernel<<<dim3((80 + 63) / 64, M / 64), 256>>>(h1, W2, b2, h2, M, 160, 80);

    gc_prep_kernel<80, 40, 40><<<gtile, 256>>>(h2, Wg1, p1, v1, ksq);
    gc_attn_kernel<80, 40, 40><<<gtile, 128, smem1>>>(p1, ksq, v1, bg1, h3);

    gc_prep_kernel<40, 5, 8><<<gtile, 256>>>(h3, Wg2, p2, v2, ksq);
    gc_attn_kernel<40, 5, 8><<<gtile, 128, smem2>>>(p2, ksq, v2, bg2, h4);

    finalize_kernel<<<BQ, 256>>>(h4, Wf, bf, out);
}

// round 4
// speedup vs baseline: 3.1143x; 1.8968x over previous
#include <cuda_runtime.h>
#include <cuda_bf16.h>
#include <math.h>
#include <stdint.h>

#define BQ 32
#define NN 2048

// Scratch (device globals; no allocations allowed)
__device__ float g_h1[BQ * NN * 160];
__device__ float g_h2[BQ * NN * 80];
__device__ float g_h3[BQ * NN * 40];
__device__ float g_h4[BQ * NN * 5];
__device__ uint2 g_pack1[BQ * NN * 40];   // bf16 (hi2,lo2) pairs of h2 (C=80 -> 40 uint2)
__device__ uint2 g_pack2[BQ * NN * 24];   // bf16 pairs of h3 (C=40 padded to 48 -> 24 uint2)
__device__ unsigned g_v1[BQ * NN * 40];   // tf32 of h2@Wg1
__device__ unsigned g_v2[BQ * NN * 8];    // tf32 of h3@Wg2 (padded to 8)
__device__ float g_ksq[BQ * NN];

// ---------------------------------------------------------------------------
// helpers
// ---------------------------------------------------------------------------
__device__ __forceinline__ uint32_t f2tf32(float x) {
    uint32_t r;
    asm("cvt.rna.tf32.f32 %0, %1;" : "=r"(r) : "f"(x));
    return r;
}

// pack (even->low16, odd->high16) as bf16x2
__device__ __forceinline__ uint32_t packbf2(float e, float o) {
    uint32_t r;
    asm("cvt.rn.bf16x2.f32 %0, %1, %2;" : "=r"(r) : "f"(o), "f"(e));
    return r;
}

__device__ __forceinline__ void mma_tf32(float c[4], const uint32_t a[4],
                                         const uint32_t b[2]) {
    asm volatile(
        "mma.sync.aligned.m16n8k8.row.col.f32.tf32.tf32.f32 "
        "{%0,%1,%2,%3}, {%4,%5,%6,%7}, {%8,%9}, {%0,%1,%2,%3};\n"
        : "+f"(c[0]), "+f"(c[1]), "+f"(c[2]), "+f"(c[3])
        : "r"(a[0]), "r"(a[1]), "r"(a[2]), "r"(a[3]), "r"(b[0]), "r"(b[1]));
}

__device__ __forceinline__ void mma_bf16(float c[4], uint32_t a0, uint32_t a1,
                                         uint32_t a2, uint32_t a3,
                                         uint32_t b0, uint32_t b1) {
    asm volatile(
        "mma.sync.aligned.m16n8k16.row.col.f32.bf16.bf16.f32 "
        "{%0,%1,%2,%3}, {%4,%5,%6,%7}, {%8,%9}, {%0,%1,%2,%3};\n"
        : "+f"(c[0]), "+f"(c[1]), "+f"(c[2]), "+f"(c[3])
        : "r"(a0), "r"(a1), "r"(a2), "r"(a3), "r"(b0), "r"(b1));
}

// split x into bf16 hi + bf16 lo (stored as the two halves of two packed regs)
__device__ __forceinline__ void split2(float xe, float xo, uint32_t& hi, uint32_t& lo) {
    float he = __bfloat162float(__float2bfloat16(xe));
    float ho = __bfloat162float(__float2bfloat16(xo));
    hi = packbf2(xe, xo);          // same RN rounding as above
    lo = packbf2(xe - he, xo - ho);
}

// ---------------------------------------------------------------------------
// MMA GEMM: C[M,N] = relu(A[M,K] @ W[K,N] + b[N]), bf16x2 3-term.
// 256 threads (8 warps), tile 128x64, BK=32.  K % 32 == 0, M % 128 == 0.
// ---------------------------------------------------------------------------
__global__ void gemm_mma_relu_kernel(const float* __restrict__ A,
                                     const float* __restrict__ W,
                                     const float* __restrict__ bias,
                                     float* __restrict__ C,
                                     int M, int K, int N) {
    constexpr int KP = 20;  // uint2 per row (16 used, pad: 20 % 8 == 4 -> conflict-free)
    __shared__ uint2 Asm[128 * KP];
    __shared__ uint2 Wsm[64 * KP];

    const int tid = threadIdx.x;
    const int lane = tid & 31, warp = tid >> 5;
    const int g = lane >> 2, t = lane & 3;
    const int m0 = blockIdx.y * 128, n0 = blockIdx.x * 64;
    const int row0 = warp * 16 + g;

    float acc[8][4];
    #pragma unroll
    for (int f = 0; f < 8; f++)
        acc[f][0] = acc[f][1] = acc[f][2] = acc[f][3] = 0.0f;

    for (int k0 = 0; k0 < K; k0 += 32) {
        // stage A: 128 rows x 16 uint2
        #pragma unroll
        for (int i = 0; i < 8; i++) {
            int idx = tid + i * 256;
            int r = idx >> 4, c2 = idx & 15;
            float2 av = *(const float2*)&A[(size_t)(m0 + r) * K + k0 + 2 * c2];
            uint32_t hi, lo;
            split2(av.x, av.y, hi, lo);
            Asm[r * KP + c2] = make_uint2(hi, lo);
        }
        // stage W: 64 cols x 16 uint2 (coalesced along n)
        #pragma unroll
        for (int i = 0; i < 4; i++) {
            int idx = tid + i * 256;
            int c2 = idx >> 6, n = idx & 63;
            float we = 0.0f, wo = 0.0f;
            if (n0 + n < N) {
                we = W[(size_t)(k0 + 2 * c2) * N + n0 + n];
                wo = W[(size_t)(k0 + 2 * c2 + 1) * N + n0 + n];
            }
            uint32_t hi, lo;
            split2(we, wo, hi, lo);
            Wsm[n * KP + c2] = make_uint2(hi, lo);
        }
        __syncthreads();

        #pragma unroll
        for (int ks = 0; ks < 16; ks += 8) {
            uint2 a0 = Asm[row0 * KP + ks + t];
            uint2 a1 = Asm[(row0 + 8) * KP + ks + t];
            uint2 a2 = Asm[row0 * KP + ks + t + 4];
            uint2 a3 = Asm[(row0 + 8) * KP + ks + t + 4];
            #pragma unroll
            for (int f = 0; f < 8; f++) {
                uint2 b0 = Wsm[(8 * f + g) * KP + ks + t];
                uint2 b1 = Wsm[(8 * f + g) * KP + ks + t + 4];
                mma_bf16(acc[f], a0.x, a1.x, a2.x, a3.x, b0.y, b1.y);  // ah*bl
                mma_bf16(acc[f], a0.y, a1.y, a2.y, a3.y, b0.x, b1.x);  // al*bh
                mma_bf16(acc[f], a0.x, a1.x, a2.x, a3.x, b0.x, b1.x);  // ah*bh
            }
        }
        __syncthreads();
    }

    // epilogue
    #pragma unroll
    for (int f = 0; f < 8; f++) {
        int c0 = n0 + 8 * f + 2 * t, c1 = c0 + 1;
        if (c0 < N) {
            float bv = bias[c0];
            C[(size_t)(m0 + row0) * N + c0] = fmaxf(acc[f][0] + bv, 0.0f);
            C[(size_t)(m0 + row0 + 8) * N + c0] = fmaxf(acc[f][2] + bv, 0.0f);
        }
        if (c1 < N) {
            float bv = bias[c1];
            C[(size_t)(m0 + row0) * N + c1] = fmaxf(acc[f][1] + bv, 0.0f);
            C[(size_t)(m0 + row0 + 8) * N + c1] = fmaxf(acc[f][3] + bv, 0.0f);
        }
    }
}

// ---------------------------------------------------------------------------
// Prep per graph-conv layer: Hpack = packed bf16 hi/lo pairs of H (k padded
// with zeros to 2*C2), ksq = |h|^2, V = tf32(H @ Wg) padded to VN columns.
// Grid: (NN/64, B), 256 threads.
// ---------------------------------------------------------------------------
template <int C, int C2, int COUT, int VN>
__global__ void gc_prep_kernel(const float* __restrict__ H,
                               const float* __restrict__ Wg,
                               uint2* __restrict__ Hpack,
                               unsigned* __restrict__ Vhi,
                               float* __restrict__ ksq_g) {
    __shared__ float Hs[64][C + 1];
    __shared__ float Wgs[C * COUT];
    const int tid = threadIdx.x;
    const int batch = blockIdx.y;
    const int n0 = blockIdx.x * 64;
    const float* Hb = H + (size_t)batch * NN * C + (size_t)n0 * C;

    for (int idx = tid; idx < 64 * C; idx += 256) {
        Hs[idx / C][idx % C] = Hb[idx];
    }
    for (int idx = tid; idx < C * COUT; idx += 256) Wgs[idx] = Wg[idx];
    __syncthreads();

    uint2* Pb = Hpack + (size_t)batch * NN * C2 + (size_t)n0 * C2;
    for (int idx = tid; idx < 64 * C2; idx += 256) {
        int r = idx / C2, c2 = idx % C2;
        float e = (2 * c2 < C) ? Hs[r][2 * c2] : 0.0f;
        float o = (2 * c2 + 1 < C) ? Hs[r][2 * c2 + 1] : 0.0f;
        uint32_t hi, lo;
        split2(e, o, hi, lo);
        Pb[idx] = make_uint2(hi, lo);
    }
    if (tid < 64) {
        float s = 0.0f;
        #pragma unroll 4
        for (int c = 0; c < C; c++) { float v = Hs[tid][c]; s += v * v; }
        ksq_g[(size_t)batch * NN + n0 + tid] = s;
    }
    unsigned* Vb = Vhi + (size_t)batch * NN * VN + (size_t)n0 * VN;
    for (int idx = tid; idx < 64 * VN; idx += 256) {
        int r = idx / VN, o = idx % VN;
        float v = 0.0f;
        if (o < COUT) {
            #pragma unroll 4
            for (int c = 0; c < C; c++) v += Hs[r][c] * Wgs[c * COUT + o];
        }
        Vb[idx] = f2tf32(v);
    }
}

// ---------------------------------------------------------------------------
// Graph-conv attention kernel. S via bf16x2 (m16n8k16, 3-term), O = P@V via
// tf32 k8. 128 threads = 4 warps, 64 query rows/block, 64-key tiles.
// logits = 2*(q.k) - |k|^2 ; Out = relu(softmax(logits) @ V + bg)
// ---------------------------------------------------------------------------
template <int C2, int KS16, int COUT, int VN>
__global__ void gc_attn_kernel(const uint2* __restrict__ Hpack,
                               const float* __restrict__ ksq_g,
                               const unsigned* __restrict__ Vhi,
                               const float* __restrict__ bg,
                               float* __restrict__ Out) {
    constexpr int CP = (C2 % 8 == 4) ? C2 : (C2 + (12 - (C2 + 4) % 8) % 8 + 4 - C2 % 1);
    // simpler: pad so CP % 8 == 4
    constexpr int CPP = ((C2 % 8) <= 4) ? (C2 - (C2 % 8) + 4) >= C2 ? (C2 - (C2 % 8) + 4) : (C2 - (C2 % 8) + 12)
                                        : (C2 - (C2 % 8) + 12);
    constexpr int VP = VN;
    constexpr int NT = VN / 8;

    extern __shared__ char smraw[];
    uint2* Qs = (uint2*)smraw;                 // [64][CPP]
    uint2* Ks = Qs + 64 * CPP;                 // [64][CPP]
    unsigned* Vs = (unsigned*)(Ks + 64 * CPP); // [64][VP]
    float* ksqs = (float*)(Vs + 64 * VP);      // [64]

    const int tid = threadIdx.x;
    const int lane = tid & 31, warp = tid >> 5;
    const int g = lane >> 2, t = lane & 3;
    const int batch = blockIdx.y;
    const int q0 = blockIdx.x * 64;
    const uint2* Hb = Hpack + (size_t)batch * NN * C2;
    const unsigned* Vb = Vhi + (size_t)batch * NN * VN;
    const float* ksqb = ksq_g + (size_t)batch * NN;

    // stage Q (once)
    for (int idx = tid; idx < 64 * C2; idx += 128) {
        int r = idx / C2, c = idx % C2;
        Qs[r * CPP + c] = Hb[(size_t)(q0 + r) * C2 + c];
    }

    const int row0 = warp * 16 + g;
    const int src0 = (lane & ~3) | (t >> 1);
    const int src2 = src0 + 2;
    const bool odd = (t & 1);

    float acc[NT][4];
    #pragma unroll
    for (int j = 0; j < NT; j++)
        acc[j][0] = acc[j][1] = acc[j][2] = acc[j][3] = 0.0f;
    float m0r = -1e30f, m1r = -1e30f, l0r = 0.0f, l1r = 0.0f;

    for (int k0 = 0; k0 < NN; k0 += 64) {
        for (int idx = tid; idx < 64 * C2; idx += 128) {
            int r = idx / C2, c = idx % C2;
            Ks[r * CPP + c] = Hb[(size_t)(k0 + r) * C2 + c];
        }
        for (int idx = tid; idx < 64 * VN; idx += 128) {
            int r = idx / VN, c = idx % VN;
            Vs[r * VP + c] = Vb[(size_t)(k0 + r) * VN + c];
        }
        if (tid < 64) ksqs[tid] = ksqb[k0 + tid];
        __syncthreads();

        // ---- S = Q @ K^T (bf16x2, 3-term) ----
        float s[8][4];
        #pragma unroll
        for (int j = 0; j < 8; j++) s[j][0] = s[j][1] = s[j][2] = s[j][3] = 0.0f;

        #pragma unroll
        for (int ks = 0; ks < KS16; ks++) {
            const int base = ks * 8;
            uint2 a0 = Qs[row0 * CPP + base + t];
            uint2 a1 = Qs[(row0 + 8) * CPP + base + t];
            uint2 a2 = Qs[row0 * CPP + base + t + 4];
            uint2 a3 = Qs[(row0 + 8) * CPP + base + t + 4];
            #pragma unroll
            for (int j = 0; j < 8; j++) {
                uint2 b0 = Ks[(8 * j + g) * CPP + base + t];
                uint2 b1 = Ks[(8 * j + g) * CPP + base + t + 4];
                mma_bf16(s[j], a0.x, a1.x, a2.x, a3.x, b0.y, b1.y);
                mma_bf16(s[j], a0.y, a1.y, a2.y, a3.y, b0.x, b1.x);
                mma_bf16(s[j], a0.x, a1.x, a2.x, a3.x, b0.x, b1.x);
            }
        }

        // ---- logits = 2*s - ksq, online softmax ----
        float mx0 = -1e30f, mx1 = -1e30f;
        #pragma unroll
        for (int j = 0; j < 8; j++) {
            float kv0 = ksqs[8 * j + 2 * t], kv1 = ksqs[8 * j + 2 * t + 1];
            s[j][0] = 2.0f * s[j][0] - kv0;
            s[j][1] = 2.0f * s[j][1] - kv1;
            s[j][2] = 2.0f * s[j][2] - kv0;
            s[j][3] = 2.0f * s[j][3] - kv1;
            mx0 = fmaxf(mx0, fmaxf(s[j][0], s[j][1]));
            mx1 = fmaxf(mx1, fmaxf(s[j][2], s[j][3]));
        }
        mx0 = fmaxf(mx0, __shfl_xor_sync(0xffffffffu, mx0, 1));
        mx0 = fmaxf(mx0, __shfl_xor_sync(0xffffffffu, mx0, 2));
        mx1 = fmaxf(mx1, __shfl_xor_sync(0xffffffffu, mx1, 1));
        mx1 = fmaxf(mx1, __shfl_xor_sync(0xffffffffu, mx1, 2));
        float nm0 = fmaxf(m0r, mx0), nm1 = fmaxf(m1r, mx1);
        float al0 = __expf(m0r - nm0), al1 = __expf(m1r - nm1);
        m0r = nm0; m1r = nm1;

        float sum0 = 0.0f, sum1 = 0.0f;
        #pragma unroll
        for (int j = 0; j < 8; j++) {
            s[j][0] = __expf(s[j][0] - nm0);
            s[j][1] = __expf(s[j][1] - nm0);
            s[j][2] = __expf(s[j][2] - nm1);
            s[j][3] = __expf(s[j][3] - nm1);
            sum0 += s[j][0] + s[j][1];
            sum1 += s[j][2] + s[j][3];
        }
        sum0 += __shfl_xor_sync(0xffffffffu, sum0, 1);
        sum0 += __shfl_xor_sync(0xffffffffu, sum0, 2);
        sum1 += __shfl_xor_sync(0xffffffffu, sum1, 1);
        sum1 += __shfl_xor_sync(0xffffffffu, sum1, 2);
        l0r = l0r * al0 + sum0;
        l1r = l1r * al1 + sum1;
        #pragma unroll
        for (int j = 0; j < NT; j++) {
            acc[j][0] *= al0; acc[j][1] *= al0;
            acc[j][2] *= al1; acc[j][3] *= al1;
        }

        // ---- O += P @ V (tf32 k8); P refragmented C-frag -> A-frag via shfl ----
        #pragma unroll
        for (int kb = 0; kb < 8; kb++) {
            uint32_t u0 = f2tf32(s[kb][0]);
            uint32_t u1 = f2tf32(s[kb][1]);
            uint32_t u2 = f2tf32(s[kb][2]);
            uint32_t u3 = f2tf32(s[kb][3]);
            uint32_t e0  = __shfl_sync(0xffffffffu, u0, src0);
            uint32_t o0  = __shfl_sync(0xffffffffu, u1, src0);
            uint32_t e0b = __shfl_sync(0xffffffffu, u0, src2);
            uint32_t o0b = __shfl_sync(0xffffffffu, u1, src2);
            uint32_t e1  = __shfl_sync(0xffffffffu, u2, src0);
            uint32_t o1  = __shfl_sync(0xffffffffu, u3, src0);
            uint32_t e1b = __shfl_sync(0xffffffffu, u2, src2);
            uint32_t o1b = __shfl_sync(0xffffffffu, u3, src2);
            uint32_t ap[4];
            ap[0] = odd ? o0 : e0;
            ap[1] = odd ? o1 : e1;
            ap[2] = odd ? o0b : e0b;
            ap[3] = odd ? o1b : e1b;
            #pragma unroll
            for (int j = 0; j < NT; j++) {
                uint32_t bp[2];
                bp[0] = Vs[(8 * kb + t) * VP + 8 * j + g];
                bp[1] = Vs[(8 * kb + t + 4) * VP + 8 * j + g];
                mma_tf32(acc[j], ap, bp);
            }
        }
        __syncthreads();
    }

    // ---- epilogue: Out = relu(acc/l + bg) ----
    float inv0 = 1.0f / l0r, inv1 = 1.0f / l1r;
    float* Outb = Out + (size_t)batch * NN * COUT + (size_t)q0 * COUT;
    #pragma unroll
    for (int j = 0; j < NT; j++) {
        int c0 = 8 * j + 2 * t, c1 = c0 + 1;
        if (c0 < COUT) {
            float b0v = __ldg(&bg[c0]);
            Outb[row0 * COUT + c0] = fmaxf(acc[j][0] * inv0 + b0v, 0.0f);
            Outb[(row0 + 8) * COUT + c0] = fmaxf(acc[j][2] * inv1 + b0v, 0.0f);
        }
        if (c1 < COUT) {
            float b1v = __ldg(&bg[c1]);
            Outb[row0 * COUT + c1] = fmaxf(acc[j][1] * inv0 + b1v, 0.0f);
            Outb[(row0 + 8) * COUT + c1] = fmaxf(acc[j][3] * inv1 + b1v, 0.0f);
        }
    }
}

// ---------------------------------------------------------------------------
// Mean over nodes -> classifier -> softmax. One block per batch.
// ---------------------------------------------------------------------------
__global__ void finalize_kernel(const float* __restrict__ H4,
                                const float* __restrict__ Wf,
                                const float* __restrict__ bf,
                                float* __restrict__ out) {
    int b = blockIdx.x;
    int tid = threadIdx.x;
    __shared__ float sred[5][256];
    float local[5] = {};
    const float* Hb = H4 + (long)b * NN * 5;
    for (int r = tid; r < NN; r += 256) {
        #pragma unroll
        for (int c = 0; c < 5; c++) local[c] += Hb[r * 5 + c];
    }
    #pragma unroll
    for (int c = 0; c < 5; c++) sred[c][tid] = local[c];
    __syncthreads();
    for (int s = 128; s > 0; s >>= 1) {
        if (tid < s) {
            #pragma unroll
            for (int c = 0; c < 5; c++) sred[c][tid] += sred[c][tid + s];
        }
        __syncthreads();
    }
    if (tid == 0) {
        float mean[5];
        #pragma unroll
        for (int c = 0; c < 5; c++) mean[c] = sred[c][0] / (float)NN;
        float lg[2];
        #pragma unroll
        for (int o = 0; o < 2; o++) {
            float v = bf[o];
            #pragma unroll
            for (int c = 0; c < 5; c++) v += mean[c] * Wf[c * 2 + o];
            lg[o] = v;
        }
        float mx = fmaxf(lg[0], lg[1]);
        float e0 = expf(lg[0] - mx), e1 = expf(lg[1] - mx);
        float inv = 1.0f / (e0 + e1);
        out[b * 2 + 0] = e0 * inv;
        out[b * 2 + 1] = e1 * inv;
    }
}

// ---------------------------------------------------------------------------

static int cpp_of(int C2) {  // pad so stride % 8 == 4 (conflict-free LDS.64)
    int r = C2 % 8;
    return (r <= 4) ? C2 - r + 4 : C2 - r + 12;
}

static size_t attn_smem_bytes(int C2, int VN) {
    int cpp = cpp_of(C2);
    return (size_t)64 * cpp * 8 * 2 + (size_t)64 * VN * 4 + 64 * 4;
}

extern "C" void kernel_launch(void* const* d_in, const int* in_sizes, int n_in,
                              void* d_out, int out_size) {
    const float* x   = (const float*)d_in[0];
    const float* W1  = (const float*)d_in[1];
    const float* b1  = (const float*)d_in[2];
    const float* W2  = (const float*)d_in[3];
    const float* b2  = (const float*)d_in[4];
    const float* Wg1 = (const float*)d_in[5];
    const float* bg1 = (const float*)d_in[6];
    const float* Wg2 = (const float*)d_in[7];
    const float* bg2 = (const float*)d_in[8];
    const float* Wf  = (const float*)d_in[9];
    const float* bf  = (const float*)d_in[10];
    float* out = (float*)d_out;

    float *h1, *h2, *h3, *h4, *ksq;
    uint2 *p1, *p2;
    unsigned *v1, *v2;
    cudaGetSymbolAddress((void**)&h1, g_h1);
    cudaGetSymbolAddress((void**)&h2, g_h2);
    cudaGetSymbolAddress((void**)&h3, g_h3);
    cudaGetSymbolAddress((void**)&h4, g_h4);
    cudaGetSymbolAddress((void**)&p1, g_pack1);
    cudaGetSymbolAddress((void**)&p2, g_pack2);
    cudaGetSymbolAddress((void**)&v1, g_v1);
    cudaGetSymbolAddress((void**)&v2, g_v2);
    cudaGetSymbolAddress((void**)&ksq, g_ksq);

    size_t smem1 = attn_smem_bytes(40, 40);
    size_t smem2 = attn_smem_bytes(24, 8);
    cudaFuncSetAttribute(gc_attn_kernel<40, 5, 40, 40>,
                         cudaFuncAttributeMaxDynamicSharedMemorySize, (int)smem1);
    cudaFuncSetAttribute(gc_attn_kernel<24, 3, 5, 8>,
                         cudaFuncAttributeMaxDynamicSharedMemorySize, (int)smem2);

    const int M = BQ * NN;  // 65536
    dim3 gtile(NN / 64, BQ);

    gemm_mma_relu_kernel<<<dim3(3, M / 128), 256>>>(x, W1, b1, h1, M, 320, 160);
    gemm_mma_relu_kernel<<<dim3(2, M / 128), 256>>>(h1, W2, b2, h2, M, 160, 80);

    gc_prep_kernel<80, 40, 40, 40><<<gtile, 256>>>(h2, Wg1, p1, v1, ksq);
    gc_attn_kernel<40, 5, 40, 40><<<gtile, 128, smem1>>>(p1, ksq, v1, bg1, h3);

    gc_prep_kernel<40, 24, 5, 8><<<gtile, 256>>>(h3, Wg2, p2, v2, ksq);
    gc_attn_kernel<24, 3, 5, 8><<<gtile, 128, smem2>>>(p2, ksq, v2, bg2, h4);

    finalize_kernel<<<BQ, 256>>>(h4, Wf, bf, out);
}

// round 7
// speedup vs baseline: 3.6693x; 1.1782x over previous
#include <cuda_runtime.h>
#include <cuda_bf16.h>
#include <math.h>
#include <stdint.h>

#define BQ 32
#define NN 2048

// Scratch (device globals; no allocations allowed)
__device__ float g_h1[BQ * NN * 160];
__device__ float g_h2[BQ * NN * 80];
__device__ float g_h3[BQ * NN * 40];
__device__ float g_h4[BQ * NN * 5];
__device__ uint2 g_pack1[BQ * NN * 40];        // bf16 (hi2,lo2) pairs of h2 (C=80)
__device__ uint2 g_pack2[BQ * NN * 24];        // bf16 pairs of h3 (C=40 pad 48)
__device__ unsigned g_vpk1[BQ * (NN / 2) * 40]; // bf16 V pairs (packed by key pair)
__device__ unsigned g_vpk2[BQ * (NN / 2) * 8];
__device__ float g_ksql[BQ * NN];              // |h|^2 * log2(e)

// ---------------------------------------------------------------------------
// helpers
// ---------------------------------------------------------------------------
#define LOG2E_F 1.4426950408889634f
#define C2E_F   2.8853900817779268f   // 2*log2(e)

__device__ __forceinline__ float ex2f(float x) {
    float r;
    asm("ex2.approx.f32 %0, %1;" : "=f"(r) : "f"(x));
    return r;
}

// pack (e -> low16, o -> high16) as bf16x2
__device__ __forceinline__ uint32_t packbf2(float e, float o) {
    uint32_t r;
    asm("cvt.rn.bf16x2.f32 %0, %1, %2;" : "=r"(r) : "f"(o), "f"(e));
    return r;
}

__device__ __forceinline__ void mma_bf16(float c[4], uint32_t a0, uint32_t a1,
                                         uint32_t a2, uint32_t a3,
                                         uint32_t b0, uint32_t b1) {
    asm volatile(
        "mma.sync.aligned.m16n8k16.row.col.f32.bf16.bf16.f32 "
        "{%0,%1,%2,%3}, {%4,%5,%6,%7}, {%8,%9}, {%0,%1,%2,%3};\n"
        : "+f"(c[0]), "+f"(c[1]), "+f"(c[2]), "+f"(c[3])
        : "r"(a0), "r"(a1), "r"(a2), "r"(a3), "r"(b0), "r"(b1));
}

// split (e,o) into bf16 hi pair + bf16 lo (residual) pair
__device__ __forceinline__ void split2(float xe, float xo, uint32_t& hi, uint32_t& lo) {
    float he = __bfloat162float(__float2bfloat16(xe));
    float ho = __bfloat162float(__float2bfloat16(xo));
    hi = packbf2(xe, xo);
    lo = packbf2(xe - he, xo - ho);
}

// ---------------------------------------------------------------------------
// MMA GEMM: C[M,N] = relu(A[M,K] @ W[K,N] + b[N]), bf16x2 3-term.
// 256 threads (8 warps), tile 128x64, BK=32.  K % 32 == 0, M % 128 == 0.
// ---------------------------------------------------------------------------
__global__ void gemm_mma_relu_kernel(const float* __restrict__ A,
                                     const float* __restrict__ W,
                                     const float* __restrict__ bias,
                                     float* __restrict__ C,
                                     int M, int K, int N) {
    constexpr int KP = 20;  // uint2 per row (16 used; 20 % 8 == 4 -> conflict-free)
    __shared__ uint2 Asm[128 * KP];
    __shared__ uint2 Wsm[64 * KP];

    const int tid = threadIdx.x;
    const int lane = tid & 31, warp = tid >> 5;
    const int g = lane >> 2, t = lane & 3;
    const int m0 = blockIdx.y * 128, n0 = blockIdx.x * 64;
    const int row0 = warp * 16 + g;

    float acc[8][4];
    #pragma unroll
    for (int f = 0; f < 8; f++)
        acc[f][0] = acc[f][1] = acc[f][2] = acc[f][3] = 0.0f;

    for (int k0 = 0; k0 < K; k0 += 32) {
        #pragma unroll
        for (int i = 0; i < 8; i++) {
            int idx = tid + i * 256;
            int r = idx >> 4, c2 = idx & 15;
            float2 av = *(const float2*)&A[(size_t)(m0 + r) * K + k0 + 2 * c2];
            uint32_t hi, lo;
            split2(av.x, av.y, hi, lo);
            Asm[r * KP + c2] = make_uint2(hi, lo);
        }
        #pragma unroll
        for (int i = 0; i < 4; i++) {
            int idx = tid + i * 256;
            int c2 = idx >> 6, n = idx & 63;
            float we = 0.0f, wo = 0.0f;
            if (n0 + n < N) {
                we = W[(size_t)(k0 + 2 * c2) * N + n0 + n];
                wo = W[(size_t)(k0 + 2 * c2 + 1) * N + n0 + n];
            }
            uint32_t hi, lo;
            split2(we, wo, hi, lo);
            Wsm[n * KP + c2] = make_uint2(hi, lo);
        }
        __syncthreads();

        #pragma unroll
        for (int ks = 0; ks < 16; ks += 8) {
            uint2 a0 = Asm[row0 * KP + ks + t];
            uint2 a1 = Asm[(row0 + 8) * KP + ks + t];
            uint2 a2 = Asm[row0 * KP + ks + t + 4];
            uint2 a3 = Asm[(row0 + 8) * KP + ks + t + 4];
            #pragma unroll
            for (int f = 0; f < 8; f++) {
                uint2 b0 = Wsm[(8 * f + g) * KP + ks + t];
                uint2 b1 = Wsm[(8 * f + g) * KP + ks + t + 4];
                mma_bf16(acc[f], a0.x, a1.x, a2.x, a3.x, b0.y, b1.y);  // ah*bl
                mma_bf16(acc[f], a0.y, a1.y, a2.y, a3.y, b0.x, b1.x);  // al*bh
                mma_bf16(acc[f], a0.x, a1.x, a2.x, a3.x, b0.x, b1.x);  // ah*bh
            }
        }
        __syncthreads();
    }

    #pragma unroll
    for (int f = 0; f < 8; f++) {
        int c0 = n0 + 8 * f + 2 * t, c1 = c0 + 1;
        if (c0 < N) {
            float bv = bias[c0];
            C[(size_t)(m0 + row0) * N + c0] = fmaxf(acc[f][0] + bv, 0.0f);
            C[(size_t)(m0 + row0 + 8) * N + c0] = fmaxf(acc[f][2] + bv, 0.0f);
        }
        if (c1 < N) {
            float bv = bias[c1];
            C[(size_t)(m0 + row0) * N + c1] = fmaxf(acc[f][1] + bv, 0.0f);
            C[(size_t)(m0 + row0 + 8) * N + c1] = fmaxf(acc[f][3] + bv, 0.0f);
        }
    }
}

// ---------------------------------------------------------------------------
// Prep per graph-conv layer:
//  Hpack = bf16 hi/lo channel pairs of H (padded to 2*C2 channels with zeros)
//  ksql  = |h|^2 * log2(e)
//  Vpk   = bf16(H @ Wg) packed by KEY PAIRS: Vpk[node/2][c] = {V[2r][c], V[2r+1][c]}
// Grid: (NN/64, B), 256 threads.
// ---------------------------------------------------------------------------
template <int C, int C2, int COUT, int VN>
__global__ void gc_prep_kernel(const float* __restrict__ H,
                               const float* __restrict__ Wg,
                               uint2* __restrict__ Hpack,
                               unsigned* __restrict__ Vpk,
                               float* __restrict__ ksql_g) {
    __shared__ float Hs[64][C + 1];
    __shared__ float Wgs[C * COUT];
    __shared__ float Vsf[64 * VN];
    const int tid = threadIdx.x;
    const int batch = blockIdx.y;
    const int n0 = blockIdx.x * 64;
    const float* Hb = H + (size_t)batch * NN * C + (size_t)n0 * C;

    for (int idx = tid; idx < 64 * C; idx += 256) {
        Hs[idx / C][idx % C] = Hb[idx];
    }
    for (int idx = tid; idx < C * COUT; idx += 256) Wgs[idx] = Wg[idx];
    __syncthreads();

    uint2* Pb = Hpack + (size_t)batch * NN * C2 + (size_t)n0 * C2;
    for (int idx = tid; idx < 64 * C2; idx += 256) {
        int r = idx / C2, c2 = idx % C2;
        float e = (2 * c2 < C) ? Hs[r][2 * c2] : 0.0f;
        float o = (2 * c2 + 1 < C) ? Hs[r][2 * c2 + 1] : 0.0f;
        uint32_t hi, lo;
        split2(e, o, hi, lo);
        Pb[idx] = make_uint2(hi, lo);
    }
    if (tid < 64) {
        float s = 0.0f;
        #pragma unroll 4
        for (int c = 0; c < C; c++) { float v = Hs[tid][c]; s += v * v; }
        ksql_g[(size_t)batch * NN + n0 + tid] = s * LOG2E_F;
    }
    for (int idx = tid; idx < 64 * VN; idx += 256) {
        int r = idx / VN, o = idx % VN;
        float v = 0.0f;
        if (o < COUT) {
            #pragma unroll 4
            for (int c = 0; c < C; c++) v += Hs[r][c] * Wgs[c * COUT + o];
        }
        Vsf[r * VN + o] = v;
    }
    __syncthreads();
    unsigned* Vb = Vpk + (size_t)batch * (NN / 2) * VN + (size_t)(n0 / 2) * VN;
    for (int idx = tid; idx < 32 * VN; idx += 256) {
        int r = idx / VN, c = idx % VN;
        Vb[idx] = packbf2(Vsf[(2 * r) * VN + c], Vsf[(2 * r + 1) * VN + c]);
    }
}

// ---------------------------------------------------------------------------
// Graph-conv attention kernel.
//  S via bf16x2 3-term (m16n8k16).  Fixed softmax max: m_row = |q|^2 (self-key
//  attains it), so p = exp(-|q-k|^2) -- no online max, no rescaling.
//  P packed straight from S C-fragments into bf16 A-fragments (zero shuffles);
//  O = P @ V via bf16 m16n8k16 (V packed by key pairs).
// 128 threads = 4 warps, 64 query rows per block, 64-key tiles.
// ---------------------------------------------------------------------------
template <int C2, int COUT, int VN, int VP>
__global__ void gc_attn_kernel(const uint2* __restrict__ Hpack,
                               const float* __restrict__ ksql_g,
                               const unsigned* __restrict__ Vpk,
                               const float* __restrict__ bg,
                               float* __restrict__ Out) {
    static_assert(C2 % 8 == 0, "");
    constexpr int KS16 = C2 / 8;      // k16 chunks for S
    constexpr int CPP = C2 + 4;       // uint2 row stride (== 4 mod 8)
    constexpr int NT = VN / 8;

    extern __shared__ char smraw[];
    uint2* Qs = (uint2*)smraw;                   // [64][CPP]
    uint2* Ks = Qs + 64 * CPP;                   // [64][CPP]
    unsigned* Vs = (unsigned*)(Ks + 64 * CPP);   // [32][VP] (key pairs x cols)
    float* ksqs = (float*)(Vs + 32 * VP);        // [64]

    const int tid = threadIdx.x;
    const int lane = tid & 31, warp = tid >> 5;
    const int g = lane >> 2, t = lane & 3;
    const int batch = blockIdx.y;
    const int q0 = blockIdx.x * 64;
    const uint2* Hb = Hpack + (size_t)batch * NN * C2;
    const unsigned* Vb = Vpk + (size_t)batch * (NN / 2) * VN;
    const float* ksqlb = ksql_g + (size_t)batch * NN;

    // stage Q (once)
    for (int idx = tid; idx < 64 * C2; idx += 128) {
        int r = idx / C2, c = idx % C2;
        Qs[r * CPP + c] = Hb[(size_t)(q0 + r) * C2 + c];
    }

    const int row0 = warp * 16 + g;
    const float ql0 = ksqlb[q0 + row0];        // |q|^2 * log2e, row g
    const float ql1 = ksqlb[q0 + row0 + 8];    // row g+8

    float acc[NT][4];
    #pragma unroll
    for (int j = 0; j < NT; j++)
        acc[j][0] = acc[j][1] = acc[j][2] = acc[j][3] = 0.0f;
    float l0r = 0.0f, l1r = 0.0f;

    for (int k0 = 0; k0 < NN; k0 += 64) {
        for (int idx = tid; idx < 64 * C2; idx += 128) {
            int r = idx / C2, c = idx % C2;
            Ks[r * CPP + c] = Hb[(size_t)(k0 + r) * C2 + c];
        }
        for (int idx = tid; idx < 32 * VN; idx += 128) {
            int r = idx / VN, c = idx % VN;
            Vs[r * VP + c] = Vb[(size_t)(k0 / 2 + r) * VN + c];
        }
        if (tid < 64) ksqs[tid] = ksqlb[k0 + tid];
        __syncthreads();

        // ---- S = Q @ K^T (bf16x2, 3-term) ----
        float s[8][4];
        #pragma unroll
        for (int j = 0; j < 8; j++) s[j][0] = s[j][1] = s[j][2] = s[j][3] = 0.0f;

        #pragma unroll
        for (int ks = 0; ks < KS16; ks++) {
            const int base = ks * 8;
            uint2 a0 = Qs[row0 * CPP + base + t];
            uint2 a1 = Qs[(row0 + 8) * CPP + base + t];
            uint2 a2 = Qs[row0 * CPP + base + t + 4];
            uint2 a3 = Qs[(row0 + 8) * CPP + base + t + 4];
            #pragma unroll
            for (int j = 0; j < 8; j++) {
                uint2 b0 = Ks[(8 * j + g) * CPP + base + t];
                uint2 b1 = Ks[(8 * j + g) * CPP + base + t + 4];
                mma_bf16(s[j], a0.x, a1.x, a2.x, a3.x, b0.y, b1.y);
                mma_bf16(s[j], a0.y, a1.y, a2.y, a3.y, b0.x, b1.x);
                mma_bf16(s[j], a0.x, a1.x, a2.x, a3.x, b0.x, b1.x);
            }
        }

        // ---- p = exp2(log2e*(2*s - ksq - qsq)); pack into bf16 A-fragments ----
        uint32_t pA[8], pB[8];
        #pragma unroll
        for (int j = 0; j < 8; j++) {
            float kl0 = ksqs[8 * j + 2 * t], kl1 = ksqs[8 * j + 2 * t + 1];
            float p00 = ex2f(fmaf(s[j][0], C2E_F, -(kl0 + ql0)));
            float p01 = ex2f(fmaf(s[j][1], C2E_F, -(kl1 + ql0)));
            float p10 = ex2f(fmaf(s[j][2], C2E_F, -(kl0 + ql1)));
            float p11 = ex2f(fmaf(s[j][3], C2E_F, -(kl1 + ql1)));
            l0r += p00 + p01;
            l1r += p10 + p11;
            pA[j] = packbf2(p00, p01);   // A[g][2t], A[g][2t+1]
            pB[j] = packbf2(p10, p11);   // A[g+8][2t], A[g+8][2t+1]
        }

        // ---- O += P @ V (bf16 m16n8k16, V packed by key pairs) ----
        #pragma unroll
        for (int kbp = 0; kbp < 4; kbp++) {
            uint32_t a0 = pA[2 * kbp], a1 = pB[2 * kbp];
            uint32_t a2 = pA[2 * kbp + 1], a3 = pB[2 * kbp + 1];
            #pragma unroll
            for (int j = 0; j < NT; j++) {
                uint32_t b0 = Vs[(8 * kbp + t) * VP + 8 * j + g];
                uint32_t b1 = Vs[(8 * kbp + t + 4) * VP + 8 * j + g];
                mma_bf16(acc[j], a0, a1, a2, a3, b0, b1);
            }
        }
        __syncthreads();
    }

    // ---- epilogue: reduce l across quad, Out = relu(acc/l + bg) ----
    l0r += __shfl_xor_sync(0xffffffffu, l0r, 1);
    l0r += __shfl_xor_sync(0xffffffffu, l0r, 2);
    l1r += __shfl_xor_sync(0xffffffffu, l1r, 1);
    l1r += __shfl_xor_sync(0xffffffffu, l1r, 2);
    float inv0 = 1.0f / l0r, inv1 = 1.0f / l1r;
    float* Outb = Out + (size_t)batch * NN * COUT + (size_t)q0 * COUT;
    #pragma unroll
    for (int j = 0; j < NT; j++) {
        int c0 = 8 * j + 2 * t, c1 = c0 + 1;
        if (c0 < COUT) {
            float b0v = __ldg(&bg[c0]);
            Outb[row0 * COUT + c0] = fmaxf(acc[j][0] * inv0 + b0v, 0.0f);
            Outb[(row0 + 8) * COUT + c0] = fmaxf(acc[j][2] * inv1 + b0v, 0.0f);
        }
        if (c1 < COUT) {
            float b1v = __ldg(&bg[c1]);
            Outb[row0 * COUT + c1] = fmaxf(acc[j][1] * inv0 + b1v, 0.0f);
            Outb[(row0 + 8) * COUT + c1] = fmaxf(acc[j][3] * inv1 + b1v, 0.0f);
        }
    }
}

// ---------------------------------------------------------------------------
// Mean over nodes -> classifier -> softmax. One block per batch.
// ---------------------------------------------------------------------------
__global__ void finalize_kernel(const float* __restrict__ H4,
                                const float* __restrict__ Wf,
                                const float* __restrict__ bf,
                                float* __restrict__ out) {
    int b = blockIdx.x;
    int tid = threadIdx.x;
    __shared__ float sred[5][256];
    float local[5] = {};
    const float* Hb = H4 + (long)b * NN * 5;
    for (int r = tid; r < NN; r += 256) {
        #pragma unroll
        for (int c = 0; c < 5; c++) local[c] += Hb[r * 5 + c];
    }
    #pragma unroll
    for (int c = 0; c < 5; c++) sred[c][tid] = local[c];
    __syncthreads();
    for (int s = 128; s > 0; s >>= 1) {
        if (tid < s) {
            #pragma unroll
            for (int c = 0; c < 5; c++) sred[c][tid] += sred[c][tid + s];
        }
        __syncthreads();
    }
    if (tid == 0) {
        float mean[5];
        #pragma unroll
        for (int c = 0; c < 5; c++) mean[c] = sred[c][0] / (float)NN;
        float lg[2];
        #pragma unroll
        for (int o = 0; o < 2; o++) {
            float v = bf[o];
            #pragma unroll
            for (int c = 0; c < 5; c++) v += mean[c] * Wf[c * 2 + o];
            lg[o] = v;
        }
        float mx = fmaxf(lg[0], lg[1]);
        float e0 = expf(lg[0] - mx), e1 = expf(lg[1] - mx);
        float inv = 1.0f / (e0 + e1);
        out[b * 2 + 0] = e0 * inv;
        out[b * 2 + 1] = e1 * inv;
    }
}

// ---------------------------------------------------------------------------

static size_t attn_smem_bytes(int C2, int VP) {
    int cpp = C2 + 4;
    return (size_t)64 * cpp * 8 * 2 + (size_t)32 * VP * 4 + 64 * 4;
}

extern "C" void kernel_launch(void* const* d_in, const int* in_sizes, int n_in,
                              void* d_out, int out_size) {
    const float* x   = (const float*)d_in[0];
    const float* W1  = (const float*)d_in[1];
    const float* b1  = (const float*)d_in[2];
    const float* W2  = (const float*)d_in[3];
    const float* b2  = (const float*)d_in[4];
    const float* Wg1 = (const float*)d_in[5];
    const float* bg1 = (const float*)d_in[6];
    const float* Wg2 = (const float*)d_in[7];
    const float* bg2 = (const float*)d_in[8];
    const float* Wf  = (const float*)d_in[9];
    const float* bf  = (const float*)d_in[10];
    float* out = (float*)d_out;

    float *h1, *h2, *h3, *h4, *ksql;
    uint2 *p1, *p2;
    unsigned *v1, *v2;
    cudaGetSymbolAddress((void**)&h1, g_h1);
    cudaGetSymbolAddress((void**)&h2, g_h2);
    cudaGetSymbolAddress((void**)&h3, g_h3);
    cudaGetSymbolAddress((void**)&h4, g_h4);
    cudaGetSymbolAddress((void**)&p1, g_pack1);
    cudaGetSymbolAddress((void**)&p2, g_pack2);
    cudaGetSymbolAddress((void**)&v1, g_vpk1);
    cudaGetSymbolAddress((void**)&v2, g_vpk2);
    cudaGetSymbolAddress((void**)&ksql, g_ksql);

    size_t smem1 = attn_smem_bytes(40, 40);
    size_t smem2 = attn_smem_bytes(24, 8);
    cudaFuncSetAttribute(gc_attn_kernel<40, 40, 40, 40>,
                         cudaFuncAttributeMaxDynamicSharedMemorySize, (int)smem1);
    cudaFuncSetAttribute(gc_attn_kernel<24, 5, 8, 8>,
                         cudaFuncAttributeMaxDynamicSharedMemorySize, (int)smem2);

    const int M = BQ * NN;  // 65536
    dim3 gtile(NN / 64, BQ);

    gemm_mma_relu_kernel<<<dim3(3, M / 128), 256>>>(x, W1, b1, h1, M, 320, 160);
    gemm_mma_relu_kernel<<<dim3(2, M / 128), 256>>>(h1, W2, b2, h2, M, 160, 80);

    gc_prep_kernel<80, 40, 40, 40><<<gtile, 256>>>(h2, Wg1, p1, v1, ksql);
    gc_attn_kernel<40, 40, 40, 40><<<gtile, 128, smem1>>>(p1, ksql, v1, bg1, h3);

    gc_prep_kernel<40, 24, 5, 8><<<gtile, 256>>>(h3, Wg2, p2, v2, ksql);
    gc_attn_kernel<24, 5, 8, 8><<<gtile, 128, smem2>>>(p2, ksql, v2, bg2, h4);

    finalize_kernel<<<BQ, 256>>>(h4, Wf, bf, out);
}